// round 6
// baseline (speedup 1.0000x reference)
#include <cuda_runtime.h>
#include <cstddef>

#define N_EMBD        256
#define N_INPUTS      66
#define N_LEVELS      8
#define AND_PER_LEVEL 4096
#define NOT_PER_LEVEL 2048
#define LEVEL_SZ      (AND_PER_LEVEL + NOT_PER_LEVEL)
#define N_HIDDEN      1024
#define N_HID_LAYERS  8
#define LN_EPS        1e-5f

// Scratch: ping-pong activation buffers (4096 x 1024 fp32 each).
__device__ float g_bufA[AND_PER_LEVEL * N_HIDDEN];
__device__ float g_bufB[AND_PER_LEVEL * N_HIDDEN];

// ---------------------------------------------------------------------------
// init: node_embd[:66] = input_embd
// ---------------------------------------------------------------------------
__global__ void init_kernel(const float* __restrict__ input_embd,
                            float* __restrict__ node_embd) {
    int i = blockIdx.x * blockDim.x + threadIdx.x;
    if (i < N_INPUTS * N_EMBD) node_embd[i] = input_embd[i];
}

// ---------------------------------------------------------------------------
// NOT nodes: node_embd[s+4096+r] = -node_embd[x_edges[s+4096+r]]
// (sources are always < s, so independent of this level's AND outputs)
// ---------------------------------------------------------------------------
__global__ void not_kernel(const int* __restrict__ x_edges,
                           float* __restrict__ node_embd, int s) {
    int row = blockIdx.x;                 // 0..2047
    int dst = s + AND_PER_LEVEL + row;
    int src = x_edges[dst];
    const float4* sp = (const float4*)(node_embd + (size_t)src * N_EMBD);
    float4*       dp = (float4*)(node_embd + (size_t)dst * N_EMBD);
    for (int c = threadIdx.x; c < N_EMBD / 4; c += blockDim.x) {
        float4 v = sp[c];
        dp[c] = make_float4(-v.x, -v.y, -v.z, -v.w);
    }
}

// ---------------------------------------------------------------------------
// Gather: H0[r] = concat(node_embd[xa[r]], node_embd[ya[r]])  -> 4096 x 512
// ---------------------------------------------------------------------------
__global__ void gather_kernel(const int* __restrict__ x_edges,
                              const int* __restrict__ y_edges,
                              const float* __restrict__ node_embd,
                              float* __restrict__ H0, int s) {
    int row = blockIdx.x;                 // 0..4095
    int xa = x_edges[s + row];
    int ya = y_edges[s + row];
    const float4* xp = (const float4*)(node_embd + (size_t)xa * N_EMBD);
    const float4* yp = (const float4*)(node_embd + (size_t)ya * N_EMBD);
    float4*       hp = (float4*)(H0 + (size_t)row * (2 * N_EMBD));
    for (int c = threadIdx.x; c < N_EMBD / 4; c += blockDim.x) {
        hp[c]                = xp[c];
        hp[N_EMBD / 4 + c]   = yp[c];
    }
}

// ---------------------------------------------------------------------------
// SGEMM: C[M,N] = act(A[M,K] @ B[K,N] + bias[N]), row-major everywhere.
// Block tile 128x128, K-step 8, 256 threads, 8x8 micro-tile per thread.
// Double-buffered smem: one __syncthreads per K-step, LDG overlapped with FMA.
// ---------------------------------------------------------------------------
template <int RELU>
__global__ __launch_bounds__(256, 2)
void gemm_kernel(const float* __restrict__ A, const float* __restrict__ B,
                 const float* __restrict__ bias, float* __restrict__ C,
                 int M, int N, int K) {
    __shared__ float As[2][8][128];   // As[buf][k][m]
    __shared__ float Bs[2][8][128];   // Bs[buf][k][n]

    const int tid = threadIdx.x;
    const int tx = tid & 15;       // 0..15  -> n micro
    const int ty = tid >> 4;       // 0..15  -> m micro
    const int bm = blockIdx.y * 128;
    const int bn = blockIdx.x * 128;

    // A-tile load mapping: 128 rows x 8 cols = 1024 floats = 256 thr x float4
    const int arow  = tid >> 1;          // 0..127
    const int acol4 = (tid & 1) * 4;     // 0 or 4
    // B-tile load mapping: 8 rows x 128 cols
    const int brow  = tid >> 5;          // 0..7
    const int bcol4 = (tid & 31) * 4;    // 0..124

    float acc[8][8];
    #pragma unroll
    for (int i = 0; i < 8; i++)
        #pragma unroll
        for (int j = 0; j < 8; j++) acc[i][j] = 0.0f;

    const float* Aptr = A + (size_t)(bm + arow) * K + acol4;
    const float* Bptr = B + (size_t)brow * N + bn + bcol4;

    // Preload tile 0 into buffer 0.
    {
        float4 av = *(const float4*)(Aptr);
        As[0][acol4 + 0][arow] = av.x;
        As[0][acol4 + 1][arow] = av.y;
        As[0][acol4 + 2][arow] = av.z;
        As[0][acol4 + 3][arow] = av.w;
        *(float4*)&Bs[0][brow][bcol4] = *(const float4*)(Bptr);
    }
    __syncthreads();

    int buf = 0;
    for (int k0 = 8; k0 < K; k0 += 8) {
        // Issue next-tile global loads first (overlap with compute below).
        float4 av = *(const float4*)(Aptr + k0);
        float4 bv = *(const float4*)(Bptr + (size_t)k0 * N);

        #pragma unroll
        for (int k = 0; k < 8; k++) {
            float ar[8], br[8];
            #pragma unroll
            for (int i = 0; i < 8; i++) ar[i] = As[buf][k][ty * 8 + i];
            #pragma unroll
            for (int j = 0; j < 8; j++) br[j] = Bs[buf][k][tx * 8 + j];
            #pragma unroll
            for (int i = 0; i < 8; i++)
                #pragma unroll
                for (int j = 0; j < 8; j++)
                    acc[i][j] = fmaf(ar[i], br[j], acc[i][j]);
        }

        int nb = buf ^ 1;
        As[nb][acol4 + 0][arow] = av.x;
        As[nb][acol4 + 1][arow] = av.y;
        As[nb][acol4 + 2][arow] = av.z;
        As[nb][acol4 + 3][arow] = av.w;
        *(float4*)&Bs[nb][brow][bcol4] = bv;
        __syncthreads();
        buf = nb;
    }

    // Final tile.
    #pragma unroll
    for (int k = 0; k < 8; k++) {
        float ar[8], br[8];
        #pragma unroll
        for (int i = 0; i < 8; i++) ar[i] = As[buf][k][ty * 8 + i];
        #pragma unroll
        for (int j = 0; j < 8; j++) br[j] = Bs[buf][k][tx * 8 + j];
        #pragma unroll
        for (int i = 0; i < 8; i++)
            #pragma unroll
            for (int j = 0; j < 8; j++)
                acc[i][j] = fmaf(ar[i], br[j], acc[i][j]);
    }

    #pragma unroll
    for (int i = 0; i < 8; i++) {
        int row = bm + ty * 8 + i;
        #pragma unroll
        for (int j = 0; j < 8; j += 4) {
            int col = bn + tx * 8 + j;
            float4 o;
            o.x = acc[i][j + 0] + bias[col + 0];
            o.y = acc[i][j + 1] + bias[col + 1];
            o.z = acc[i][j + 2] + bias[col + 2];
            o.w = acc[i][j + 3] + bias[col + 3];
            if (RELU) {
                o.x = fmaxf(o.x, 0.0f); o.y = fmaxf(o.y, 0.0f);
                o.z = fmaxf(o.z, 0.0f); o.w = fmaxf(o.w, 0.0f);
            }
            *(float4*)(C + (size_t)row * N + col) = o;
        }
    }
}

// ---------------------------------------------------------------------------
// LayerNorm over last dim (256) + scatter into node_embd[s + row].
// One block (256 threads) per row.
// ---------------------------------------------------------------------------
__global__ void ln_kernel(const float* __restrict__ X,
                          const float* __restrict__ g,
                          const float* __restrict__ b,
                          float* __restrict__ node_embd, int s) {
    int row = blockIdx.x;                 // 0..4095
    int t = threadIdx.x;                  // 0..255
    float v = X[(size_t)row * N_EMBD + t];

    __shared__ float s1[8], s2[8];
    float a = v, q = v * v;
    #pragma unroll
    for (int o = 16; o > 0; o >>= 1) {
        a += __shfl_down_sync(0xffffffffu, a, o);
        q += __shfl_down_sync(0xffffffffu, q, o);
    }
    if ((t & 31) == 0) { s1[t >> 5] = a; s2[t >> 5] = q; }
    __syncthreads();
    float tot = 0.0f, tot2 = 0.0f;
    #pragma unroll
    for (int w = 0; w < 8; w++) { tot += s1[w]; tot2 += s2[w]; }
    float mu  = tot * (1.0f / N_EMBD);
    float var = tot2 * (1.0f / N_EMBD) - mu * mu;
    float r = rsqrtf(var + LN_EPS);
    node_embd[(size_t)(s + row) * N_EMBD + t] = (v - mu) * r * g[t] + b[t];
}

// ---------------------------------------------------------------------------
// Launch
// ---------------------------------------------------------------------------
extern "C" void kernel_launch(void* const* d_in, const int* in_sizes, int n_in,
                              void* d_out, int out_size) {
    // metadata order: nodes, x_edges, y_edges, input_embd, W_in, b_in,
    //                 W_hid, b_hid, W_out, b_out, ln_g, ln_b
    const int*   x_edges    = (const int*)d_in[1];
    const int*   y_edges    = (const int*)d_in[2];
    const float* input_embd = (const float*)d_in[3];
    const float* W_in       = (const float*)d_in[4];
    const float* b_in       = (const float*)d_in[5];
    const float* W_hid      = (const float*)d_in[6];
    const float* b_hid      = (const float*)d_in[7];
    const float* W_out      = (const float*)d_in[8];
    const float* b_out      = (const float*)d_in[9];
    const float* ln_g       = (const float*)d_in[10];
    const float* ln_b       = (const float*)d_in[11];
    float* node = (float*)d_out;

    float *bufA = nullptr, *bufB = nullptr;
    cudaGetSymbolAddress((void**)&bufA, g_bufA);
    cudaGetSymbolAddress((void**)&bufB, g_bufB);

    init_kernel<<<(N_INPUTS * N_EMBD + 255) / 256, 256>>>(input_embd, node);

    const dim3 gridH(N_HIDDEN / 128, AND_PER_LEVEL / 128);  // (8, 32)
    const dim3 gridO(N_EMBD  / 128, AND_PER_LEVEL / 128);   // (2, 32)

    for (int l = 0; l < N_LEVELS; l++) {
        int s = N_INPUTS + l * LEVEL_SZ;

        not_kernel<<<NOT_PER_LEVEL, 64>>>(x_edges, node, s);
        gather_kernel<<<AND_PER_LEVEL, 64>>>(x_edges, y_edges, node, bufA, s);

        // layer 0: (4096x512) @ (512x1024) -> bufB
        gemm_kernel<1><<<gridH, 256>>>(bufA, W_in, b_in, bufB,
                                       AND_PER_LEVEL, N_HIDDEN, 2 * N_EMBD);

        const float* cur = bufB;
        float*       nxt = bufA;
        for (int i = 0; i < N_HID_LAYERS; i++) {
            gemm_kernel<1><<<gridH, 256>>>(cur,
                                           W_hid + (size_t)i * N_HIDDEN * N_HIDDEN,
                                           b_hid + (size_t)i * N_HIDDEN,
                                           nxt, AND_PER_LEVEL, N_HIDDEN, N_HIDDEN);
            const float* t = cur; cur = nxt; nxt = (float*)t;
        }
        // after 8 layers: cur == bufB, nxt == bufA

        // output layer: (4096x1024) @ (1024x256) -> bufA (no relu)
        gemm_kernel<0><<<gridO, 256>>>(cur, W_out, b_out, nxt,
                                       AND_PER_LEVEL, N_EMBD, N_HIDDEN);

        ln_kernel<<<AND_PER_LEVEL, 256>>>(nxt, ln_g, ln_b, node, s);
    }
}

// round 11
// speedup vs baseline: 2.0407x; 2.0407x over previous
#include <cuda_runtime.h>
#include <cuda_bf16.h>
#include <cstdint>
#include <cstddef>

#define N_EMBD        256
#define N_INPUTS      66
#define N_LEVELS      8
#define AND_PER_LEVEL 4096
#define NOT_PER_LEVEL 2048
#define LEVEL_SZ      (AND_PER_LEVEL + NOT_PER_LEVEL)
#define N_HIDDEN      1024
#define N_HID_LAYERS  8
#define LN_EPS        1e-5f
#define M_ROWS        4096

// ---------------------------------------------------------------------------
// Scratch (static device arrays; no allocation).
// Split-bf16: x ~= hi + lo (each bf16) => ~16 mantissa bits.
// Weights stored transposed: W^T[N][K].
// ---------------------------------------------------------------------------
__device__ __nv_bfloat16 g_WinT_hi[N_HIDDEN * 2 * N_EMBD];
__device__ __nv_bfloat16 g_WinT_lo[N_HIDDEN * 2 * N_EMBD];
__device__ __nv_bfloat16 g_WhidT_hi[N_HID_LAYERS * N_HIDDEN * N_HIDDEN];
__device__ __nv_bfloat16 g_WhidT_lo[N_HID_LAYERS * N_HIDDEN * N_HIDDEN];
__device__ __nv_bfloat16 g_WoutT_hi[N_EMBD * N_HIDDEN];
__device__ __nv_bfloat16 g_WoutT_lo[N_EMBD * N_HIDDEN];
__device__ __nv_bfloat16 g_H0_hi[M_ROWS * 2 * N_EMBD];
__device__ __nv_bfloat16 g_H0_lo[M_ROWS * 2 * N_EMBD];
__device__ __nv_bfloat16 g_actA_hi[M_ROWS * N_HIDDEN];
__device__ __nv_bfloat16 g_actA_lo[M_ROWS * N_HIDDEN];
__device__ __nv_bfloat16 g_actB_hi[M_ROWS * N_HIDDEN];
__device__ __nv_bfloat16 g_actB_lo[M_ROWS * N_HIDDEN];
__device__ float         g_out[M_ROWS * N_EMBD];

// ---------------------------------------------------------------------------
// Base-ISA helpers (all sm_80+ features, valid under compute_103 base target)
// ---------------------------------------------------------------------------
__device__ __forceinline__ uint32_t smem_to_u32(const void* p) {
    uint32_t a;
    asm("{ .reg .u64 t; cvta.to.shared.u64 t, %1; cvt.u32.u64 %0, t; }" : "=r"(a) : "l"(p));
    return a;
}
__device__ __forceinline__ void cp_async16(uint32_t dst, const void* src) {
    asm volatile("cp.async.cg.shared.global [%0], [%1], 16;" :: "r"(dst), "l"(src));
}
__device__ __forceinline__ void cp_commit() { asm volatile("cp.async.commit_group;"); }
template <int N> __device__ __forceinline__ void cp_wait() {
    asm volatile("cp.async.wait_group %0;" :: "n"(N));
}
__device__ __forceinline__ uint32_t ld32(const __nv_bfloat16* base, int elem_off) {
    return *reinterpret_cast<const uint32_t*>(base + elem_off);
}
// m16n8k16 row.col bf16 MMA, fp32 accumulate.
__device__ __forceinline__ void mma16816(float* c, uint32_t a0, uint32_t a1, uint32_t a2,
                                         uint32_t a3, uint32_t b0, uint32_t b1) {
    asm volatile(
        "mma.sync.aligned.m16n8k16.row.col.f32.bf16.bf16.f32 "
        "{%0,%1,%2,%3}, {%4,%5,%6,%7}, {%8,%9}, {%0,%1,%2,%3};"
        : "+f"(c[0]), "+f"(c[1]), "+f"(c[2]), "+f"(c[3])
        : "r"(a0), "r"(a1), "r"(a2), "r"(a3), "r"(b0), "r"(b1));
}

// ---------------------------------------------------------------------------
// GEMM tiling constants
//   CTA tile 128(M) x 128(N); 8 warps as 2(M) x 4(N); warp tile 64x32.
//   K staged 32 per iteration, double-buffered cp.async.
//   smem row pitch KP=40 bf16 (=80B=5x16B chunks): 16B-aligned cp.async dsts,
//   conflict-free fragment loads (word idx grp*20+tig covers all 32 banks).
// ---------------------------------------------------------------------------
#define KP           40
#define TILE_BYTES   (128 * KP * 2)        // 10240
#define STAGE_BYTES  (4 * TILE_BYTES)      // 40960 (Ahi, Alo, Bhi, Blo)
#define GEMM_SMEM    (2 * STAGE_BYTES)     // 81920

template <int EPI>
__global__ __launch_bounds__(256)
void mlp_gemm(const __nv_bfloat16* __restrict__ Ah, const __nv_bfloat16* __restrict__ Al,
              const __nv_bfloat16* __restrict__ Bh, const __nv_bfloat16* __restrict__ Bl,
              const float* __restrict__ bias,
              __nv_bfloat16* __restrict__ Ch, __nv_bfloat16* __restrict__ Cl,
              float* __restrict__ Cf, int Nt, int K) {
    extern __shared__ char smem[];
    const uint32_t sb = smem_to_u32(smem);
    const int tid = threadIdx.x;
    const int lid = tid & 31;
    const int wid = tid >> 5;
    const int grp = lid >> 2;        // 0..7
    const int tig = lid & 3;         // 0..3
    const int bm = blockIdx.y * 128;
    const int bn = blockIdx.x * 128;
    const int m0w = (wid >> 2) * 64; // warp M offset in CTA tile
    const int n0w = (wid & 3) * 32;  // warp N offset

    const __nv_bfloat16* gb[4] = { Ah + (size_t)bm * K, Al + (size_t)bm * K,
                                   Bh + (size_t)bn * K, Bl + (size_t)bn * K };

    float acc[4][4][4];
    #pragma unroll
    for (int i = 0; i < 4; i++)
        #pragma unroll
        for (int j = 0; j < 4; j++)
            #pragma unroll
            for (int q = 0; q < 4; q++) acc[i][j][q] = 0.0f;

    // Async fill of one stage: 4 tiles x 128 rows x 4 16B-chunks = 2048 chunks.
    auto fill = [&](int buf, int k0) {
        const uint32_t s0 = sb + (uint32_t)buf * STAGE_BYTES;
        #pragma unroll
        for (int i = 0; i < 8; i++) {
            int idx = tid + i * 256;          // 0..2047
            int t   = idx >> 9;               // tile 0..3
            int j   = idx & 511;
            int r   = j >> 2;                 // row 0..127
            int c   = j & 3;                  // 16B chunk 0..3
            uint32_t dst = s0 + (uint32_t)t * TILE_BYTES + (uint32_t)(r * KP + c * 8) * 2;
            cp_async16(dst, gb[t] + (size_t)r * K + k0 + c * 8);
        }
    };

    const int S = K >> 5;            // stages of K=32
    fill(0, 0);
    cp_commit();

    for (int s = 0; s < S; s++) {
        if (s + 1 < S) {
            fill((s + 1) & 1, (s + 1) << 5);
            cp_commit();
            cp_wait<1>();            // stage s done; s+1 may remain in flight
        } else {
            cp_wait<0>();
        }
        __syncthreads();

        const char* st = smem + (s & 1) * STAGE_BYTES;
        const __nv_bfloat16* As_hi = (const __nv_bfloat16*)(st + 0 * TILE_BYTES);
        const __nv_bfloat16* As_lo = (const __nv_bfloat16*)(st + 1 * TILE_BYTES);
        const __nv_bfloat16* Bs_hi = (const __nv_bfloat16*)(st + 2 * TILE_BYTES);
        const __nv_bfloat16* Bs_lo = (const __nv_bfloat16*)(st + 3 * TILE_BYTES);

        #pragma unroll
        for (int kk = 0; kk < 32; kk += 16) {
            uint32_t bh[4][2], bl[4][2];
            #pragma unroll
            for (int nt = 0; nt < 4; nt++) {
                int n = n0w + nt * 8 + grp;
                bh[nt][0] = ld32(Bs_hi, n * KP + kk + tig * 2);
                bh[nt][1] = ld32(Bs_hi, n * KP + kk + 8 + tig * 2);
                bl[nt][0] = ld32(Bs_lo, n * KP + kk + tig * 2);
                bl[nt][1] = ld32(Bs_lo, n * KP + kk + 8 + tig * 2);
            }
            #pragma unroll
            for (int mt = 0; mt < 4; mt++) {
                int m = m0w + mt * 16 + grp;
                uint32_t a0 = ld32(As_hi, m * KP + kk + tig * 2);
                uint32_t a1 = ld32(As_hi, (m + 8) * KP + kk + tig * 2);
                uint32_t a2 = ld32(As_hi, m * KP + kk + 8 + tig * 2);
                uint32_t a3 = ld32(As_hi, (m + 8) * KP + kk + 8 + tig * 2);
                uint32_t l0 = ld32(As_lo, m * KP + kk + tig * 2);
                uint32_t l1 = ld32(As_lo, (m + 8) * KP + kk + tig * 2);
                uint32_t l2 = ld32(As_lo, m * KP + kk + 8 + tig * 2);
                uint32_t l3 = ld32(As_lo, (m + 8) * KP + kk + 8 + tig * 2);
                #pragma unroll
                for (int nt = 0; nt < 4; nt++) {
                    mma16816(acc[mt][nt], a0, a1, a2, a3, bh[nt][0], bh[nt][1]);
                    mma16816(acc[mt][nt], a0, a1, a2, a3, bl[nt][0], bl[nt][1]);
                    mma16816(acc[mt][nt], l0, l1, l2, l3, bh[nt][0], bh[nt][1]);
                }
            }
        }
        __syncthreads();
    }

    // Epilogue. C fragment mapping: c0,c1 -> row grp, cols tig*2,+1; c2,c3 -> row grp+8.
    #pragma unroll
    for (int mt = 0; mt < 4; mt++) {
        int r0 = bm + m0w + mt * 16 + grp;
        #pragma unroll
        for (int nt = 0; nt < 4; nt++) {
            int c0 = bn + n0w + nt * 8 + tig * 2;
            float b0v = __ldg(bias + c0);
            float b1v = __ldg(bias + c0 + 1);
            float v00 = acc[mt][nt][0] + b0v, v01 = acc[mt][nt][1] + b1v;
            float v10 = acc[mt][nt][2] + b0v, v11 = acc[mt][nt][3] + b1v;
            if (EPI == 1) {
                v00 = fmaxf(v00, 0.0f); v01 = fmaxf(v01, 0.0f);
                v10 = fmaxf(v10, 0.0f); v11 = fmaxf(v11, 0.0f);
                __nv_bfloat16 h00 = __float2bfloat16(v00), h01 = __float2bfloat16(v01);
                __nv_bfloat16 h10 = __float2bfloat16(v10), h11 = __float2bfloat16(v11);
                __nv_bfloat162 hp0; hp0.x = h00; hp0.y = h01;
                __nv_bfloat162 hp1; hp1.x = h10; hp1.y = h11;
                __nv_bfloat162 lp0;
                lp0.x = __float2bfloat16(v00 - __bfloat162float(h00));
                lp0.y = __float2bfloat16(v01 - __bfloat162float(h01));
                __nv_bfloat162 lp1;
                lp1.x = __float2bfloat16(v10 - __bfloat162float(h10));
                lp1.y = __float2bfloat16(v11 - __bfloat162float(h11));
                *(__nv_bfloat162*)(Ch + (size_t)r0 * Nt + c0)       = hp0;
                *(__nv_bfloat162*)(Ch + (size_t)(r0 + 8) * Nt + c0) = hp1;
                *(__nv_bfloat162*)(Cl + (size_t)r0 * Nt + c0)       = lp0;
                *(__nv_bfloat162*)(Cl + (size_t)(r0 + 8) * Nt + c0) = lp1;
            } else {
                float2 f0 = make_float2(v00, v01);
                float2 f1 = make_float2(v10, v11);
                *(float2*)(Cf + (size_t)r0 * Nt + c0)       = f0;
                *(float2*)(Cf + (size_t)(r0 + 8) * Nt + c0) = f1;
            }
        }
    }
}

// ---------------------------------------------------------------------------
// Weight transpose + split: src fp32 [K][N] -> dst bf16 hi/lo [N][K]
// ---------------------------------------------------------------------------
__global__ void tsplit_kernel(const float* __restrict__ src,
                              __nv_bfloat16* __restrict__ dh, __nv_bfloat16* __restrict__ dl,
                              int N, int K) {
    int idx = blockIdx.x * 256 + threadIdx.x;
    if (idx >= N * K) return;
    int n = idx / K;
    int k = idx - n * K;
    float v = src[(size_t)k * N + n];
    __nv_bfloat16 h = __float2bfloat16(v);
    dh[idx] = h;
    dl[idx] = __float2bfloat16(v - __bfloat162float(h));
}

// ---------------------------------------------------------------------------
// init / not / gather(split) / layernorm
// ---------------------------------------------------------------------------
__global__ void init_kernel(const float* __restrict__ input_embd, float* __restrict__ node) {
    int i = blockIdx.x * blockDim.x + threadIdx.x;
    if (i < N_INPUTS * N_EMBD) node[i] = input_embd[i];
}

__global__ void not_kernel(const int* __restrict__ x_edges, float* __restrict__ node, int s) {
    int row = blockIdx.x;
    int dst = s + AND_PER_LEVEL + row;
    int src = x_edges[dst];
    const float4* sp = (const float4*)(node + (size_t)src * N_EMBD);
    float4*       dp = (float4*)(node + (size_t)dst * N_EMBD);
    for (int c = threadIdx.x; c < N_EMBD / 4; c += blockDim.x) {
        float4 v = sp[c];
        dp[c] = make_float4(-v.x, -v.y, -v.z, -v.w);
    }
}

__global__ void gather_split_kernel(const int* __restrict__ x_edges, const int* __restrict__ y_edges,
                                    const float* __restrict__ node,
                                    __nv_bfloat16* __restrict__ Hh, __nv_bfloat16* __restrict__ Hl,
                                    int s) {
    int row = blockIdx.x;
    int xa = x_edges[s + row];
    int ya = y_edges[s + row];
    int c = threadIdx.x * 4;              // 64 threads x 4 cols
    const float4 vx = *(const float4*)(node + (size_t)xa * N_EMBD + c);
    const float4 vy = *(const float4*)(node + (size_t)ya * N_EMBD + c);
    size_t base = (size_t)row * (2 * N_EMBD);
    float xs[4] = {vx.x, vx.y, vx.z, vx.w};
    float ys[4] = {vy.x, vy.y, vy.z, vy.w};
    #pragma unroll
    for (int j = 0; j < 4; j++) {
        __nv_bfloat16 h = __float2bfloat16(xs[j]);
        Hh[base + c + j] = h;
        Hl[base + c + j] = __float2bfloat16(xs[j] - __bfloat162float(h));
        __nv_bfloat16 h2 = __float2bfloat16(ys[j]);
        Hh[base + N_EMBD + c + j] = h2;
        Hl[base + N_EMBD + c + j] = __float2bfloat16(ys[j] - __bfloat162float(h2));
    }
}

__global__ void ln_kernel(const float* __restrict__ X, const float* __restrict__ g,
                          const float* __restrict__ b, float* __restrict__ node, int s) {
    int row = blockIdx.x;
    int t = threadIdx.x;
    float v = X[(size_t)row * N_EMBD + t];
    __shared__ float s1[8], s2[8];
    float a = v, q = v * v;
    #pragma unroll
    for (int o = 16; o > 0; o >>= 1) {
        a += __shfl_down_sync(0xffffffffu, a, o);
        q += __shfl_down_sync(0xffffffffu, q, o);
    }
    if ((t & 31) == 0) { s1[t >> 5] = a; s2[t >> 5] = q; }
    __syncthreads();
    float tot = 0.0f, tot2 = 0.0f;
    #pragma unroll
    for (int w = 0; w < 8; w++) { tot += s1[w]; tot2 += s2[w]; }
    float mu  = tot * (1.0f / N_EMBD);
    float var = tot2 * (1.0f / N_EMBD) - mu * mu;
    float r = rsqrtf(var + LN_EPS);
    node[(size_t)(s + row) * N_EMBD + t] = (v - mu) * r * g[t] + b[t];
}

// ---------------------------------------------------------------------------
// Launch
// ---------------------------------------------------------------------------
extern "C" void kernel_launch(void* const* d_in, const int* in_sizes, int n_in,
                              void* d_out, int out_size) {
    const int*   x_edges    = (const int*)d_in[1];
    const int*   y_edges    = (const int*)d_in[2];
    const float* input_embd = (const float*)d_in[3];
    const float* W_in       = (const float*)d_in[4];
    const float* b_in       = (const float*)d_in[5];
    const float* W_hid      = (const float*)d_in[6];
    const float* b_hid      = (const float*)d_in[7];
    const float* W_out      = (const float*)d_in[8];
    const float* b_out      = (const float*)d_in[9];
    const float* ln_g       = (const float*)d_in[10];
    const float* ln_b       = (const float*)d_in[11];
    float* node = (float*)d_out;

    __nv_bfloat16 *WinTh, *WinTl, *WhidTh, *WhidTl, *WoutTh, *WoutTl;
    __nv_bfloat16 *H0h, *H0l, *aAh, *aAl, *aBh, *aBl;
    float* outp;
    cudaGetSymbolAddress((void**)&WinTh, g_WinT_hi);   cudaGetSymbolAddress((void**)&WinTl, g_WinT_lo);
    cudaGetSymbolAddress((void**)&WhidTh, g_WhidT_hi); cudaGetSymbolAddress((void**)&WhidTl, g_WhidT_lo);
    cudaGetSymbolAddress((void**)&WoutTh, g_WoutT_hi); cudaGetSymbolAddress((void**)&WoutTl, g_WoutT_lo);
    cudaGetSymbolAddress((void**)&H0h, g_H0_hi);       cudaGetSymbolAddress((void**)&H0l, g_H0_lo);
    cudaGetSymbolAddress((void**)&aAh, g_actA_hi);     cudaGetSymbolAddress((void**)&aAl, g_actA_lo);
    cudaGetSymbolAddress((void**)&aBh, g_actB_hi);     cudaGetSymbolAddress((void**)&aBl, g_actB_lo);
    cudaGetSymbolAddress((void**)&outp, g_out);

    cudaFuncSetAttribute(mlp_gemm<1>, cudaFuncAttributeMaxDynamicSharedMemorySize, GEMM_SMEM);
    cudaFuncSetAttribute(mlp_gemm<0>, cudaFuncAttributeMaxDynamicSharedMemorySize, GEMM_SMEM);

    // Weight transpose+split (once per launch; reused by all 8 levels).
    tsplit_kernel<<<(N_HIDDEN * 2 * N_EMBD + 255) / 256, 256>>>(W_in, WinTh, WinTl, N_HIDDEN, 2 * N_EMBD);
    for (int i = 0; i < N_HID_LAYERS; i++) {
        tsplit_kernel<<<(N_HIDDEN * N_HIDDEN + 255) / 256, 256>>>(
            W_hid + (size_t)i * N_HIDDEN * N_HIDDEN,
            WhidTh + (size_t)i * N_HIDDEN * N_HIDDEN,
            WhidTl + (size_t)i * N_HIDDEN * N_HIDDEN, N_HIDDEN, N_HIDDEN);
    }
    tsplit_kernel<<<(N_EMBD * N_HIDDEN + 255) / 256, 256>>>(W_out, WoutTh, WoutTl, N_EMBD, N_HIDDEN);

    init_kernel<<<(N_INPUTS * N_EMBD + 255) / 256, 256>>>(input_embd, node);

    const dim3 gridH(N_HIDDEN / 128, M_ROWS / 128);   // (8, 32)
    const dim3 gridO(N_EMBD / 128, M_ROWS / 128);     // (2, 32)

    for (int l = 0; l < N_LEVELS; l++) {
        int s = N_INPUTS + l * LEVEL_SZ;

        not_kernel<<<NOT_PER_LEVEL, 64>>>(x_edges, node, s);
        gather_split_kernel<<<AND_PER_LEVEL, 64>>>(x_edges, y_edges, node, H0h, H0l, s);

        // input layer: [4096,512] @ [512,1024]
        mlp_gemm<1><<<gridH, 256, GEMM_SMEM>>>(H0h, H0l, WinTh, WinTl, b_in,
                                               aAh, aAl, nullptr, N_HIDDEN, 2 * N_EMBD);

        __nv_bfloat16 *ch = aAh, *cl = aAl, *nh = aBh, *nl = aBl;
        for (int i = 0; i < N_HID_LAYERS; i++) {
            mlp_gemm<1><<<gridH, 256, GEMM_SMEM>>>(
                ch, cl,
                WhidTh + (size_t)i * N_HIDDEN * N_HIDDEN,
                WhidTl + (size_t)i * N_HIDDEN * N_HIDDEN,
                b_hid + (size_t)i * N_HIDDEN,
                nh, nl, nullptr, N_HIDDEN, N_HIDDEN);
            __nv_bfloat16* t;
            t = ch; ch = nh; nh = t;
            t = cl; cl = nl; nl = t;
        }

        // output layer: [4096,1024] @ [1024,256] -> fp32 (no relu)
        mlp_gemm<0><<<gridO, 256, GEMM_SMEM>>>(ch, cl, WoutTh, WoutTl, b_out,
                                               nullptr, nullptr, outp, N_EMBD, N_HIDDEN);

        ln_kernel<<<AND_PER_LEVEL, 256>>>(outp, ln_g, ln_b, node, s);
    }
}

// round 14
// speedup vs baseline: 2.0983x; 1.0282x over previous
#include <cuda_runtime.h>
#include <cuda_bf16.h>
#include <cstdint>
#include <cstddef>

#define N_EMBD        256
#define N_INPUTS      66
#define N_LEVELS      8
#define AND_PER_LEVEL 4096
#define NOT_PER_LEVEL 2048
#define LEVEL_SZ      (AND_PER_LEVEL + NOT_PER_LEVEL)
#define N_HIDDEN      1024
#define N_HID_LAYERS  8
#define LN_EPS        1e-5f
#define M_ROWS        4096

// ---------------------------------------------------------------------------
// Scratch (static device arrays; no allocation).
// Split-bf16: x ~= hi + lo (each bf16) => ~16 mantissa bits.
// Weights stored transposed: W^T[N][K].
// ---------------------------------------------------------------------------
__device__ __nv_bfloat16 g_WinT_hi[N_HIDDEN * 2 * N_EMBD];
__device__ __nv_bfloat16 g_WinT_lo[N_HIDDEN * 2 * N_EMBD];
__device__ __nv_bfloat16 g_WhidT_hi[N_HID_LAYERS * N_HIDDEN * N_HIDDEN];
__device__ __nv_bfloat16 g_WhidT_lo[N_HID_LAYERS * N_HIDDEN * N_HIDDEN];
__device__ __nv_bfloat16 g_WoutT_hi[N_EMBD * N_HIDDEN];
__device__ __nv_bfloat16 g_WoutT_lo[N_EMBD * N_HIDDEN];
__device__ __nv_bfloat16 g_H0_hi[M_ROWS * 2 * N_EMBD];
__device__ __nv_bfloat16 g_H0_lo[M_ROWS * 2 * N_EMBD];
__device__ __nv_bfloat16 g_actA_hi[M_ROWS * N_HIDDEN];
__device__ __nv_bfloat16 g_actA_lo[M_ROWS * N_HIDDEN];
__device__ __nv_bfloat16 g_actB_hi[M_ROWS * N_HIDDEN];
__device__ __nv_bfloat16 g_actB_lo[M_ROWS * N_HIDDEN];
__device__ float         g_out[M_ROWS * N_EMBD];

// ---------------------------------------------------------------------------
// Base-ISA helpers (all sm_75/80 features — legal under compute_103 base)
// ---------------------------------------------------------------------------
__device__ __forceinline__ uint32_t smem_to_u32(const void* p) {
    uint32_t a;
    asm("{ .reg .u64 t; cvta.to.shared.u64 t, %1; cvt.u32.u64 %0, t; }" : "=r"(a) : "l"(p));
    return a;
}
__device__ __forceinline__ void cp_async16(uint32_t dst, const void* src) {
    asm volatile("cp.async.cg.shared.global [%0], [%1], 16;" :: "r"(dst), "l"(src));
}
__device__ __forceinline__ void cp_commit() { asm volatile("cp.async.commit_group;"); }
template <int N> __device__ __forceinline__ void cp_wait() {
    asm volatile("cp.async.wait_group %0;" :: "n"(N));
}
__device__ __forceinline__ void ldsm_x4(uint32_t addr, uint32_t& r0, uint32_t& r1,
                                        uint32_t& r2, uint32_t& r3) {
    asm volatile("ldmatrix.sync.aligned.m8n8.x4.shared.b16 {%0,%1,%2,%3}, [%4];"
                 : "=r"(r0), "=r"(r1), "=r"(r2), "=r"(r3) : "r"(addr));
}
// m16n8k16 row.col bf16 MMA, fp32 accumulate.
__device__ __forceinline__ void mma16816(float* c, uint32_t a0, uint32_t a1, uint32_t a2,
                                         uint32_t a3, uint32_t b0, uint32_t b1) {
    asm volatile(
        "mma.sync.aligned.m16n8k16.row.col.f32.bf16.bf16.f32 "
        "{%0,%1,%2,%3}, {%4,%5,%6,%7}, {%8,%9}, {%0,%1,%2,%3};"
        : "+f"(c[0]), "+f"(c[1]), "+f"(c[2]), "+f"(c[3])
        : "r"(a0), "r"(a1), "r"(a2), "r"(a3), "r"(b0), "r"(b1));
}

// ---------------------------------------------------------------------------
// GEMM tiling:
//   CTA tile 128(M) x 128(N); 512 threads = 16 warps as 4(M) x 4(N);
//   warp tile 32x32 (mt in {0,1} of 16 rows; nt in {0..3} of 8 cols).
//   K staged 32 per iteration, double-buffered cp.async.
//   Fragments via ldmatrix.x4. smem pitch KP=40 bf16 (80B): 16B-aligned,
//   row-start bank = i*20 mod 32 -> ldmatrix rows conflict-free.
// ---------------------------------------------------------------------------
#define KP           40
#define TILE_BYTES   (128 * KP * 2)        // 10240
#define STAGE_BYTES  (4 * TILE_BYTES)      // 40960 (Ahi, Alo, Bhi, Blo)
#define GEMM_SMEM    (2 * STAGE_BYTES)     // 81920

template <int EPI>
__global__ __launch_bounds__(512)
void mlp_gemm(const __nv_bfloat16* __restrict__ Ah, const __nv_bfloat16* __restrict__ Al,
              const __nv_bfloat16* __restrict__ Bh, const __nv_bfloat16* __restrict__ Bl,
              const float* __restrict__ bias,
              __nv_bfloat16* __restrict__ Ch, __nv_bfloat16* __restrict__ Cl,
              float* __restrict__ Cf, int Nt, int K) {
    extern __shared__ char smem[];
    const uint32_t sb = smem_to_u32(smem);
    const int tid = threadIdx.x;
    const int lid = tid & 31;
    const int wid = tid >> 5;
    const int grp = lid >> 2;        // 0..7
    const int tig = lid & 3;         // 0..3
    const int bm = blockIdx.y * 128;
    const int bn = blockIdx.x * 128;
    const int m0w = (wid >> 2) * 32; // warp M offset (4 warp-rows)
    const int n0w = (wid & 3) * 32;  // warp N offset (4 warp-cols)

    // ldmatrix per-thread address components (element units).
    // A x4 mats: [(m0,k0),(m8,k0),(m0,k8),(m8,k8)]
    const int a_row = m0w + ((lid >> 3) & 1) * 8 + (lid & 7);
    const int a_kad = (lid >> 4) * 8;
    // B x4 mats: [(nA,k0),(nA,k8),(nA+8,k0),(nA+8,k8)]
    const int b_row = n0w + ((lid >> 4) & 1) * 8 + (lid & 7);
    const int b_kad = ((lid >> 3) & 1) * 8;

    const __nv_bfloat16* gb[4] = { Ah + (size_t)bm * K, Al + (size_t)bm * K,
                                   Bh + (size_t)bn * K, Bl + (size_t)bn * K };

    float acc[2][4][4];
    #pragma unroll
    for (int i = 0; i < 2; i++)
        #pragma unroll
        for (int j = 0; j < 4; j++)
            #pragma unroll
            for (int q = 0; q < 4; q++) acc[i][j][q] = 0.0f;

    // Async fill of one stage: 4 tiles x 128 rows x 4 16B-chunks = 2048 chunks.
    auto fill = [&](int buf, int k0) {
        const uint32_t s0 = sb + (uint32_t)buf * STAGE_BYTES;
        #pragma unroll
        for (int i = 0; i < 4; i++) {
            int idx = tid + i * 512;          // 0..2047
            int t   = idx >> 9;               // tile 0..3
            int j   = idx & 511;
            int r   = j >> 2;                 // row 0..127
            int c   = j & 3;                  // 16B chunk 0..3
            uint32_t dst = s0 + (uint32_t)t * TILE_BYTES + (uint32_t)(r * KP + c * 8) * 2;
            cp_async16(dst, gb[t] + (size_t)r * K + k0 + c * 8);
        }
    };

    const int S = K >> 5;            // stages of K=32
    fill(0, 0);
    cp_commit();

    for (int s = 0; s < S; s++) {
        if (s + 1 < S) {
            fill((s + 1) & 1, (s + 1) << 5);
            cp_commit();
            cp_wait<1>();            // stage s done; s+1 may remain in flight
        } else {
            cp_wait<0>();
        }
        __syncthreads();

        const uint32_t st = sb + (uint32_t)(s & 1) * STAGE_BYTES;
        const uint32_t Ahi = st;
        const uint32_t Alo = st + TILE_BYTES;
        const uint32_t Bhi = st + 2 * TILE_BYTES;
        const uint32_t Blo = st + 3 * TILE_BYTES;

        #pragma unroll
        for (int kk = 0; kk < 32; kk += 16) {
            // B fragments: 2 ldmatrix.x4 each for hi/lo cover nt=0..3.
            uint32_t bh[4][2], bl[4][2];
            #pragma unroll
            for (int p = 0; p < 2; p++) {
                uint32_t off = (uint32_t)((b_row + p * 16) * KP + kk + b_kad) * 2;
                ldsm_x4(Bhi + off, bh[2*p][0], bh[2*p][1], bh[2*p+1][0], bh[2*p+1][1]);
                ldsm_x4(Blo + off, bl[2*p][0], bl[2*p][1], bl[2*p+1][0], bl[2*p+1][1]);
            }
            // A fragments + MMAs per mt.
            #pragma unroll
            for (int mt = 0; mt < 2; mt++) {
                uint32_t off = (uint32_t)((a_row + mt * 16) * KP + kk + a_kad) * 2;
                uint32_t a0, a1, a2, a3, l0, l1, l2, l3;
                ldsm_x4(Ahi + off, a0, a1, a2, a3);
                ldsm_x4(Alo + off, l0, l1, l2, l3);
                #pragma unroll
                for (int nt = 0; nt < 4; nt++) {
                    mma16816(acc[mt][nt], a0, a1, a2, a3, bh[nt][0], bh[nt][1]);
                    mma16816(acc[mt][nt], a0, a1, a2, a3, bl[nt][0], bl[nt][1]);
                    mma16816(acc[mt][nt], l0, l1, l2, l3, bh[nt][0], bh[nt][1]);
                }
            }
        }
        __syncthreads();
    }

    // Epilogue. C frag: c0,c1 -> (row grp, cols tig*2,+1); c2,c3 -> row grp+8.
    #pragma unroll
    for (int mt = 0; mt < 2; mt++) {
        int r0 = bm + m0w + mt * 16 + grp;
        #pragma unroll
        for (int nt = 0; nt < 4; nt++) {
            int c0 = bn + n0w + nt * 8 + tig * 2;
            float b0v = __ldg(bias + c0);
            float b1v = __ldg(bias + c0 + 1);
            float v00 = acc[mt][nt][0] + b0v, v01 = acc[mt][nt][1] + b1v;
            float v10 = acc[mt][nt][2] + b0v, v11 = acc[mt][nt][3] + b1v;
            if (EPI == 1) {
                v00 = fmaxf(v00, 0.0f); v01 = fmaxf(v01, 0.0f);
                v10 = fmaxf(v10, 0.0f); v11 = fmaxf(v11, 0.0f);
                __nv_bfloat16 h00 = __float2bfloat16(v00), h01 = __float2bfloat16(v01);
                __nv_bfloat16 h10 = __float2bfloat16(v10), h11 = __float2bfloat16(v11);
                __nv_bfloat162 hp0; hp0.x = h00; hp0.y = h01;
                __nv_bfloat162 hp1; hp1.x = h10; hp1.y = h11;
                __nv_bfloat162 lp0;
                lp0.x = __float2bfloat16(v00 - __bfloat162float(h00));
                lp0.y = __float2bfloat16(v01 - __bfloat162float(h01));
                __nv_bfloat162 lp1;
                lp1.x = __float2bfloat16(v10 - __bfloat162float(h10));
                lp1.y = __float2bfloat16(v11 - __bfloat162float(h11));
                *(__nv_bfloat162*)(Ch + (size_t)r0 * Nt + c0)       = hp0;
                *(__nv_bfloat162*)(Ch + (size_t)(r0 + 8) * Nt + c0) = hp1;
                *(__nv_bfloat162*)(Cl + (size_t)r0 * Nt + c0)       = lp0;
                *(__nv_bfloat162*)(Cl + (size_t)(r0 + 8) * Nt + c0) = lp1;
            } else {
                *(float2*)(Cf + (size_t)r0 * Nt + c0)       = make_float2(v00, v01);
                *(float2*)(Cf + (size_t)(r0 + 8) * Nt + c0) = make_float2(v10, v11);
            }
        }
    }
}

// ---------------------------------------------------------------------------
// Weight transpose + split: src fp32 [K][N] -> dst bf16 hi/lo [N][K]
// ---------------------------------------------------------------------------
__global__ void tsplit_kernel(const float* __restrict__ src,
                              __nv_bfloat16* __restrict__ dh, __nv_bfloat16* __restrict__ dl,
                              int N, int K) {
    int idx = blockIdx.x * 256 + threadIdx.x;
    if (idx >= N * K) return;
    int n = idx / K;
    int k = idx - n * K;
    float v = src[(size_t)k * N + n];
    __nv_bfloat16 h = __float2bfloat16(v);
    dh[idx] = h;
    dl[idx] = __float2bfloat16(v - __bfloat162float(h));
}

// ---------------------------------------------------------------------------
// init / fused not+gather / layernorm
// ---------------------------------------------------------------------------
__global__ void init_kernel(const float* __restrict__ input_embd, float* __restrict__ node) {
    int i = blockIdx.x * blockDim.x + threadIdx.x;
    if (i < N_INPUTS * N_EMBD) node[i] = input_embd[i];
}

// rows [0,4096): gather+split into H0;  rows [4096,6144): NOT-copy into node.
__global__ void gather_not_kernel(const int* __restrict__ x_edges, const int* __restrict__ y_edges,
                                  const float* __restrict__ node_c, float* __restrict__ node,
                                  __nv_bfloat16* __restrict__ Hh, __nv_bfloat16* __restrict__ Hl,
                                  int s) {
    int row = blockIdx.x;
    int c = threadIdx.x * 4;              // 64 threads x 4 cols
    if (row < AND_PER_LEVEL) {
        int xa = x_edges[s + row];
        int ya = y_edges[s + row];
        const float4 vx = *(const float4*)(node_c + (size_t)xa * N_EMBD + c);
        const float4 vy = *(const float4*)(node_c + (size_t)ya * N_EMBD + c);
        size_t base = (size_t)row * (2 * N_EMBD);
        float xs[4] = {vx.x, vx.y, vx.z, vx.w};
        float ys[4] = {vy.x, vy.y, vy.z, vy.w};
        #pragma unroll
        for (int j = 0; j < 4; j++) {
            __nv_bfloat16 h = __float2bfloat16(xs[j]);
            Hh[base + c + j] = h;
            Hl[base + c + j] = __float2bfloat16(xs[j] - __bfloat162float(h));
            __nv_bfloat16 h2 = __float2bfloat16(ys[j]);
            Hh[base + N_EMBD + c + j] = h2;
            Hl[base + N_EMBD + c + j] = __float2bfloat16(ys[j] - __bfloat162float(h2));
        }
    } else {
        int dst = s + row;                // row >= 4096 -> NOT node index s+row
        int src = x_edges[dst];
        float4 v = *(const float4*)(node_c + (size_t)src * N_EMBD + c);
        *(float4*)(node + (size_t)dst * N_EMBD + c) = make_float4(-v.x, -v.y, -v.z, -v.w);
    }
}

__global__ void ln_kernel(const float* __restrict__ X, const float* __restrict__ g,
                          const float* __restrict__ b, float* __restrict__ node, int s) {
    int row = blockIdx.x;
    int t = threadIdx.x;
    float v = X[(size_t)row * N_EMBD + t];
    __shared__ float s1[8], s2[8];
    float a = v, q = v * v;
    #pragma unroll
    for (int o = 16; o > 0; o >>= 1) {
        a += __shfl_down_sync(0xffffffffu, a, o);
        q += __shfl_down_sync(0xffffffffu, q, o);
    }
    if ((t & 31) == 0) { s1[t >> 5] = a; s2[t >> 5] = q; }
    __syncthreads();
    float tot = 0.0f, tot2 = 0.0f;
    #pragma unroll
    for (int w = 0; w < 8; w++) { tot += s1[w]; tot2 += s2[w]; }
    float mu  = tot * (1.0f / N_EMBD);
    float var = tot2 * (1.0f / N_EMBD) - mu * mu;
    float r = rsqrtf(var + LN_EPS);
    node[(size_t)(s + row) * N_EMBD + t] = (v - mu) * r * g[t] + b[t];
}

// ---------------------------------------------------------------------------
// Launch
// ---------------------------------------------------------------------------
extern "C" void kernel_launch(void* const* d_in, const int* in_sizes, int n_in,
                              void* d_out, int out_size) {
    const int*   x_edges    = (const int*)d_in[1];
    const int*   y_edges    = (const int*)d_in[2];
    const float* input_embd = (const float*)d_in[3];
    const float* W_in       = (const float*)d_in[4];
    const float* b_in       = (const float*)d_in[5];
    const float* W_hid      = (const float*)d_in[6];
    const float* b_hid      = (const float*)d_in[7];
    const float* W_out      = (const float*)d_in[8];
    const float* b_out      = (const float*)d_in[9];
    const float* ln_g       = (const float*)d_in[10];
    const float* ln_b       = (const float*)d_in[11];
    float* node = (float*)d_out;

    __nv_bfloat16 *WinTh, *WinTl, *WhidTh, *WhidTl, *WoutTh, *WoutTl;
    __nv_bfloat16 *H0h, *H0l, *aAh, *aAl, *aBh, *aBl;
    float* outp;
    cudaGetSymbolAddress((void**)&WinTh, g_WinT_hi);   cudaGetSymbolAddress((void**)&WinTl, g_WinT_lo);
    cudaGetSymbolAddress((void**)&WhidTh, g_WhidT_hi); cudaGetSymbolAddress((void**)&WhidTl, g_WhidT_lo);
    cudaGetSymbolAddress((void**)&WoutTh, g_WoutT_hi); cudaGetSymbolAddress((void**)&WoutTl, g_WoutT_lo);
    cudaGetSymbolAddress((void**)&H0h, g_H0_hi);       cudaGetSymbolAddress((void**)&H0l, g_H0_lo);
    cudaGetSymbolAddress((void**)&aAh, g_actA_hi);     cudaGetSymbolAddress((void**)&aAl, g_actA_lo);
    cudaGetSymbolAddress((void**)&aBh, g_actB_hi);     cudaGetSymbolAddress((void**)&aBl, g_actB_lo);
    cudaGetSymbolAddress((void**)&outp, g_out);

    cudaFuncSetAttribute(mlp_gemm<1>, cudaFuncAttributeMaxDynamicSharedMemorySize, GEMM_SMEM);
    cudaFuncSetAttribute(mlp_gemm<0>, cudaFuncAttributeMaxDynamicSharedMemorySize, GEMM_SMEM);

    // Weight transpose+split (once per launch; reused by all 8 levels).
    tsplit_kernel<<<(N_HIDDEN * 2 * N_EMBD + 255) / 256, 256>>>(W_in, WinTh, WinTl, N_HIDDEN, 2 * N_EMBD);
    for (int i = 0; i < N_HID_LAYERS; i++) {
        tsplit_kernel<<<(N_HIDDEN * N_HIDDEN + 255) / 256, 256>>>(
            W_hid + (size_t)i * N_HIDDEN * N_HIDDEN,
            WhidTh + (size_t)i * N_HIDDEN * N_HIDDEN,
            WhidTl + (size_t)i * N_HIDDEN * N_HIDDEN, N_HIDDEN, N_HIDDEN);
    }
    tsplit_kernel<<<(N_EMBD * N_HIDDEN + 255) / 256, 256>>>(W_out, WoutTh, WoutTl, N_EMBD, N_HIDDEN);

    init_kernel<<<(N_INPUTS * N_EMBD + 255) / 256, 256>>>(input_embd, node);

    const dim3 gridH(N_HIDDEN / 128, M_ROWS / 128);   // (8, 32)
    const dim3 gridO(N_EMBD / 128, M_ROWS / 128);     // (2, 32)

    for (int l = 0; l < N_LEVELS; l++) {
        int s = N_INPUTS + l * LEVEL_SZ;

        gather_not_kernel<<<LEVEL_SZ, 64>>>(x_edges, y_edges, node, node, H0h, H0l, s);

        // input layer: [4096,512] @ [512,1024]
        mlp_gemm<1><<<gridH, 512, GEMM_SMEM>>>(H0h, H0l, WinTh, WinTl, b_in,
                                               aAh, aAl, nullptr, N_HIDDEN, 2 * N_EMBD);

        __nv_bfloat16 *ch = aAh, *cl = aAl, *nh = aBh, *nl = aBl;
        for (int i = 0; i < N_HID_LAYERS; i++) {
            mlp_gemm<1><<<gridH, 512, GEMM_SMEM>>>(
                ch, cl,
                WhidTh + (size_t)i * N_HIDDEN * N_HIDDEN,
                WhidTl + (size_t)i * N_HIDDEN * N_HIDDEN,
                b_hid + (size_t)i * N_HIDDEN,
                nh, nl, nullptr, N_HIDDEN, N_HIDDEN);
            __nv_bfloat16* t;
            t = ch; ch = nh; nh = t;
            t = cl; cl = nl; nl = t;
        }

        // output layer: [4096,1024] @ [1024,256] -> fp32 (no relu)
        mlp_gemm<0><<<gridO, 512, GEMM_SMEM>>>(ch, cl, WoutTh, WoutTl, b_out,
                                               nullptr, nullptr, outp, N_EMBD, N_HIDDEN);

        ln_kernel<<<AND_PER_LEVEL, 256>>>(outp, ln_g, ln_b, node, s);
    }
}